// round 1
// baseline (speedup 1.0000x reference)
#include <cuda_runtime.h>
#include <math.h>

#define B_ 8
#define S_ 1024
#define D_ 1024
#define H_ 16
#define DK_ 64

// Scratch (device globals: allocation-free)
__device__ float g_q[B_*H_*S_*DK_];    // [B,H,S,DK]
__device__ float g_k[B_*H_*S_*DK_];
__device__ float g_v[B_*H_*S_*DK_];
__device__ float g_ctx[B_*S_*D_];      // [B,S,D]

// ---------------------------------------------------------------------------
// SGEMM: Y[m,n] = sum_k X[m,k]*W[n,k] + bias[n]
// X: [M=8192, K=1024] row-major, W: [N=1024, K=1024] row-major (torch Linear)
// TRANS_OUT: write Y to [B,H,S,DK] layout (m -> (b,s), n -> (h,dk))
// Tiling: 128x128 block, BK=8, 256 threads, 8x8 per thread.
// ---------------------------------------------------------------------------
template<bool TRANS_OUT>
__global__ __launch_bounds__(256) void sgemm_bias_kernel(
    const float* __restrict__ X, const float* __restrict__ W,
    const float* __restrict__ bias, float* __restrict__ Y)
{
    constexpr int Kd = D_;
    __shared__ float As[8][128];
    __shared__ float Bs[8][128];

    const int tid = threadIdx.x;
    const int tx = tid & 15;          // n-group
    const int ty = tid >> 4;          // m-group
    const int m0 = blockIdx.y * 128;
    const int n0 = blockIdx.x * 128;

    const int loadRow = tid >> 1;          // 0..127
    const int loadCol = (tid & 1) * 4;     // 0 or 4
    const float* xPtr = X + (size_t)(m0 + loadRow) * Kd + loadCol;
    const float* wPtr = W + (size_t)(n0 + loadRow) * Kd + loadCol;

    float acc[8][8];
    #pragma unroll
    for (int i = 0; i < 8; i++)
        #pragma unroll
        for (int j = 0; j < 8; j++) acc[i][j] = 0.f;

    for (int k0 = 0; k0 < Kd; k0 += 8) {
        float4 xv = *(const float4*)(xPtr + k0);
        float4 wv = *(const float4*)(wPtr + k0);
        As[loadCol + 0][loadRow] = xv.x;
        As[loadCol + 1][loadRow] = xv.y;
        As[loadCol + 2][loadRow] = xv.z;
        As[loadCol + 3][loadRow] = xv.w;
        Bs[loadCol + 0][loadRow] = wv.x;
        Bs[loadCol + 1][loadRow] = wv.y;
        Bs[loadCol + 2][loadRow] = wv.z;
        Bs[loadCol + 3][loadRow] = wv.w;
        __syncthreads();

        #pragma unroll
        for (int kk = 0; kk < 8; kk++) {
            float a[8], b[8];
            *(float4*)&a[0] = *(const float4*)&As[kk][ty * 8];
            *(float4*)&a[4] = *(const float4*)&As[kk][ty * 8 + 4];
            *(float4*)&b[0] = *(const float4*)&Bs[kk][tx * 8];
            *(float4*)&b[4] = *(const float4*)&Bs[kk][tx * 8 + 4];
            #pragma unroll
            for (int i = 0; i < 8; i++)
                #pragma unroll
                for (int j = 0; j < 8; j++)
                    acc[i][j] += a[i] * b[j];
        }
        __syncthreads();
    }

    #pragma unroll
    for (int i = 0; i < 8; i++) {
        const int m = m0 + ty * 8 + i;
        #pragma unroll
        for (int j = 0; j < 8; j++) {
            const int n = n0 + tx * 8 + j;
            const float v = acc[i][j] + __ldg(&bias[n]);
            if (TRANS_OUT) {
                const int b_ = m >> 10;          // S_=1024
                const int s_ = m & 1023;
                const int h_ = n >> 6;           // DK_=64
                const int dk_ = n & 63;
                Y[(((size_t)(b_ * H_ + h_)) * S_ + s_) * DK_ + dk_] = v;
            } else {
                Y[(size_t)m * D_ + n] = v;
            }
        }
    }
}

// ---------------------------------------------------------------------------
// Flash attention (fp32). Grid: (S/64, B*H). 256 threads.
// Per block: 64 query rows, loop over 16 key blocks of 64.
// Thread (ty,tx): rows 4ty..4ty+3, cols 4tx..4tx+3 (scores) / dims 4tx.. (O).
// Half-warp (16 lanes, same ty) owns a row group -> shfl reductions.
// ---------------------------------------------------------------------------
#define PAD 68

__global__ __launch_bounds__(256) void flash_attn_kernel(
    const float* __restrict__ Qg_, const float* __restrict__ Kg_,
    const float* __restrict__ Vg_, const int* __restrict__ mask,
    float* __restrict__ Out)
{
    extern __shared__ float sm[];
    float* Qs = sm;                 // [dk][q]  stride PAD (transposed)
    float* Ks = sm + 64 * PAD;      // [dk][k]  stride PAD (transposed)
    float* Vs = sm + 2 * 64 * PAD;  // [k][dk]  stride PAD (natural)
    float* Ps = sm + 3 * 64 * PAD;  // [q][k]   stride PAD

    const int bh = blockIdx.y;            // 0..127
    const int b = bh >> 4;
    const int h = bh & 15;
    const int q0 = blockIdx.x * 64;
    const int tid = threadIdx.x;
    const int tx = tid & 15;
    const int ty = tid >> 4;

    const float* Qg = Qg_ + (size_t)bh * S_ * DK_;
    const float* Kg = Kg_ + (size_t)bh * S_ * DK_;
    const float* Vg = Vg_ + (size_t)bh * S_ * DK_;
    const int* Mg = mask + (size_t)b * S_ * S_;

    // Load Q tile transposed: Qs[dk][q]
    #pragma unroll
    for (int rep = 0; rep < 4; rep++) {
        const int idx = rep * 256 + tid;
        const int row = idx >> 4;            // 0..63
        const int col = (idx & 15) << 2;     // 0..60
        float4 qv = *(const float4*)(Qg + (size_t)(q0 + row) * DK_ + col);
        Qs[(col + 0) * PAD + row] = qv.x;
        Qs[(col + 1) * PAD + row] = qv.y;
        Qs[(col + 2) * PAD + row] = qv.z;
        Qs[(col + 3) * PAD + row] = qv.w;
    }

    float O[4][4];
    float mrow[4], lrow[4];
    #pragma unroll
    for (int i = 0; i < 4; i++) {
        mrow[i] = -1e30f;
        lrow[i] = 0.f;
        #pragma unroll
        for (int d = 0; d < 4; d++) O[i][d] = 0.f;
    }

    for (int k0 = 0; k0 < S_; k0 += 64) {
        __syncthreads();  // previous PV done before overwriting K/V/P
        // Load K transposed, V natural
        #pragma unroll
        for (int rep = 0; rep < 4; rep++) {
            const int idx = rep * 256 + tid;
            const int row = idx >> 4;
            const int col = (idx & 15) << 2;
            float4 kv = *(const float4*)(Kg + (size_t)(k0 + row) * DK_ + col);
            Ks[(col + 0) * PAD + row] = kv.x;
            Ks[(col + 1) * PAD + row] = kv.y;
            Ks[(col + 2) * PAD + row] = kv.z;
            Ks[(col + 3) * PAD + row] = kv.w;
            float4 vv = *(const float4*)(Vg + (size_t)(k0 + row) * DK_ + col);
            *(float4*)&Vs[row * PAD + col] = vv;
        }
        __syncthreads();

        // Scores: s[i][j] = Q[4ty+i] . K[4tx+j]
        float s[4][4];
        #pragma unroll
        for (int i = 0; i < 4; i++)
            #pragma unroll
            for (int j = 0; j < 4; j++) s[i][j] = 0.f;

        #pragma unroll 16
        for (int d = 0; d < 64; d++) {
            float4 qv = *(const float4*)&Qs[d * PAD + ty * 4];
            float4 kv = *(const float4*)&Ks[d * PAD + tx * 4];
            const float qa[4] = {qv.x, qv.y, qv.z, qv.w};
            const float ka[4] = {kv.x, kv.y, kv.z, kv.w};
            #pragma unroll
            for (int i = 0; i < 4; i++)
                #pragma unroll
                for (int j = 0; j < 4; j++)
                    s[i][j] += qa[i] * ka[j];
        }

        // Scale + mask
        #pragma unroll
        for (int i = 0; i < 4; i++) {
            const int4 mv = *(const int4*)(Mg + (size_t)(q0 + ty * 4 + i) * S_ + k0 + tx * 4);
            s[i][0] = mv.x ? s[i][0] * 0.125f : -1e30f;
            s[i][1] = mv.y ? s[i][1] * 0.125f : -1e30f;
            s[i][2] = mv.z ? s[i][2] * 0.125f : -1e30f;
            s[i][3] = mv.w ? s[i][3] * 0.125f : -1e30f;
        }

        // Online softmax (per row; 16-lane shfl reduction)
        #pragma unroll
        for (int i = 0; i < 4; i++) {
            float rm = fmaxf(fmaxf(s[i][0], s[i][1]), fmaxf(s[i][2], s[i][3]));
            #pragma unroll
            for (int off = 1; off < 16; off <<= 1)
                rm = fmaxf(rm, __shfl_xor_sync(0xffffffffu, rm, off));
            const float mnew = fmaxf(mrow[i], rm);
            const float corr = __expf(mrow[i] - mnew);
            mrow[i] = mnew;
            float rs = 0.f;
            #pragma unroll
            for (int j = 0; j < 4; j++) {
                const float p = __expf(s[i][j] - mnew);
                s[i][j] = p;
                rs += p;
            }
            #pragma unroll
            for (int off = 1; off < 16; off <<= 1)
                rs += __shfl_xor_sync(0xffffffffu, rs, off);
            lrow[i] = lrow[i] * corr + rs;
            #pragma unroll
            for (int d = 0; d < 4; d++) O[i][d] *= corr;
            *(float4*)&Ps[(ty * 4 + i) * PAD + tx * 4] =
                make_float4(s[i][0], s[i][1], s[i][2], s[i][3]);
        }
        __syncthreads();

        // PV: O[i][d] += sum_k P[4ty+i][k] * V[k][4tx+d]
        #pragma unroll 8
        for (int kk = 0; kk < 64; kk++) {
            float4 vv = *(const float4*)&Vs[kk * PAD + tx * 4];
            const float va[4] = {vv.x, vv.y, vv.z, vv.w};
            #pragma unroll
            for (int i = 0; i < 4; i++) {
                const float p = Ps[(ty * 4 + i) * PAD + kk];
                #pragma unroll
                for (int d = 0; d < 4; d++)
                    O[i][d] += p * va[d];
            }
        }
    }

    // Epilogue: normalize, write [B,S,D] with D = h*64 + dk
    #pragma unroll
    for (int i = 0; i < 4; i++) {
        const float inv = 1.f / lrow[i];
        float4 o4 = make_float4(O[i][0] * inv, O[i][1] * inv,
                                O[i][2] * inv, O[i][3] * inv);
        *(float4*)(Out + ((size_t)(b * S_ + q0 + ty * 4 + i)) * D_ + h * 64 + tx * 4) = o4;
    }
}

// ---------------------------------------------------------------------------
extern "C" void kernel_launch(void* const* d_in, const int* in_sizes, int n_in,
                              void* d_out, int out_size) {
    const float* query = (const float*)d_in[0];
    const float* key   = (const float*)d_in[1];
    const float* value = (const float*)d_in[2];
    const int*   mask  = (const int*)d_in[3];
    const float* wq = (const float*)d_in[4];
    const float* bq = (const float*)d_in[5];
    const float* wk = (const float*)d_in[6];
    const float* bk = (const float*)d_in[7];
    const float* wv = (const float*)d_in[8];
    const float* bv = (const float*)d_in[9];
    const float* wo = (const float*)d_in[10];
    const float* bo = (const float*)d_in[11];
    float* out = (float*)d_out;

    float *q_p, *k_p, *v_p, *ctx_p;
    cudaGetSymbolAddress((void**)&q_p, g_q);
    cudaGetSymbolAddress((void**)&k_p, g_k);
    cudaGetSymbolAddress((void**)&v_p, g_v);
    cudaGetSymbolAddress((void**)&ctx_p, g_ctx);

    const dim3 gemmGrid(D_ / 128, (B_ * S_) / 128);  // (8, 64)
    sgemm_bias_kernel<true><<<gemmGrid, 256>>>(query, wq, bq, q_p);
    sgemm_bias_kernel<true><<<gemmGrid, 256>>>(key,   wk, bk, k_p);
    sgemm_bias_kernel<true><<<gemmGrid, 256>>>(value, wv, bv, v_p);

    const int smemBytes = 4 * 64 * PAD * (int)sizeof(float);  // 69632
    cudaFuncSetAttribute(flash_attn_kernel,
                         cudaFuncAttributeMaxDynamicSharedMemorySize, smemBytes);
    flash_attn_kernel<<<dim3(S_ / 64, B_ * H_), 256, smemBytes>>>(
        q_p, k_p, v_p, mask, ctx_p);

    sgemm_bias_kernel<false><<<gemmGrid, 256>>>(ctx_p, wo, bo, out);
}

// round 3
// speedup vs baseline: 1.7203x; 1.7203x over previous
#include <cuda_runtime.h>
#include <cuda_bf16.h>
#include <cstdint>
#include <math.h>

#define B_ 8
#define S_ 1024
#define D_ 1024
#define H_ 16
#define DK_ 64

// ---------------------------------------------------------------------------
// Scratch (device globals: allocation-free)
// ---------------------------------------------------------------------------
__device__ float g_q[B_*H_*S_*DK_];    // [B,H,S,DK]
__device__ float g_k[B_*H_*S_*DK_];
__device__ float g_v[B_*H_*S_*DK_];
__device__ float g_ctx[B_*S_*D_];      // [B,S,D]
// bf16 split operands (plain row-major [M,1024])
__device__ __align__(256) __nv_bfloat16 g_ahi[8192*1024];
__device__ __align__(256) __nv_bfloat16 g_alo[8192*1024];
__device__ __align__(256) __nv_bfloat16 g_bhi[1024*1024];
__device__ __align__(256) __nv_bfloat16 g_blo[1024*1024];

// ---------------------------------------------------------------------------
// PTX helpers (base compute_103 features only: cp.async / ldmatrix / mma.sync)
// ---------------------------------------------------------------------------
__device__ __forceinline__ uint32_t smem_u32(const void* p) {
    uint32_t a;
    asm("{ .reg .u64 t; cvta.to.shared.u64 t, %1; cvt.u32.u64 %0, t; }" : "=r"(a) : "l"(p));
    return a;
}
__device__ __forceinline__ void cp_async16(uint32_t saddr, const void* gaddr) {
    asm volatile("cp.async.cg.shared.global [%0], [%1], 16;" :: "r"(saddr), "l"(gaddr));
}
__device__ __forceinline__ void cp_commit() {
    asm volatile("cp.async.commit_group;" ::: "memory");
}
template<int N>
__device__ __forceinline__ void cp_wait() {
    asm volatile("cp.async.wait_group %0;" :: "n"(N) : "memory");
}
__device__ __forceinline__ void ldsm_x4(uint32_t* r, uint32_t addr) {
    asm volatile("ldmatrix.sync.aligned.m8n8.x4.shared.b16 {%0,%1,%2,%3}, [%4];"
                 : "=r"(r[0]), "=r"(r[1]), "=r"(r[2]), "=r"(r[3]) : "r"(addr));
}
__device__ __forceinline__ void ldsm_x2(uint32_t* r, uint32_t addr) {
    asm volatile("ldmatrix.sync.aligned.m8n8.x2.shared.b16 {%0,%1}, [%2];"
                 : "=r"(r[0]), "=r"(r[1]) : "r"(addr));
}
__device__ __forceinline__ void mma_bf16(float* d, const uint32_t* a, const uint32_t* b) {
    asm volatile(
        "mma.sync.aligned.m16n8k16.row.col.f32.bf16.bf16.f32 "
        "{%0,%1,%2,%3}, {%4,%5,%6,%7}, {%8,%9}, {%0,%1,%2,%3};"
        : "+f"(d[0]), "+f"(d[1]), "+f"(d[2]), "+f"(d[3])
        : "r"(a[0]), "r"(a[1]), "r"(a[2]), "r"(a[3]), "r"(b[0]), "r"(b[1]));
}

// ---------------------------------------------------------------------------
// Split-bf16 conversion: src [M,1024] fp32 -> hi/lo bf16, row-major.
// One thread: 8 consecutive elements.
// ---------------------------------------------------------------------------
__global__ __launch_bounds__(256) void conv_split_kernel(
    const float* __restrict__ src,
    __nv_bfloat16* __restrict__ hi, __nv_bfloat16* __restrict__ lo)
{
    const size_t g = ((size_t)blockIdx.x * 256 + threadIdx.x) * 8;
    const float4 a0 = *(const float4*)(src + g);
    const float4 a1 = *(const float4*)(src + g + 4);
    const float av[8] = {a0.x, a0.y, a0.z, a0.w, a1.x, a1.y, a1.z, a1.w};

    __align__(16) __nv_bfloat16 hv[8];
    __align__(16) __nv_bfloat16 lv[8];
    #pragma unroll
    for (int i = 0; i < 8; i++) {
        hv[i] = __float2bfloat16(av[i]);
        lv[i] = __float2bfloat16(av[i] - __bfloat162float(hv[i]));
    }
    *(uint4*)(hi + g) = *(const uint4*)hv;
    *(uint4*)(lo + g) = *(const uint4*)lv;
}

// ---------------------------------------------------------------------------
// HMMA bf16x3 GEMM: Y[m,n] = sum_k X[m,k]*W[n,k] + bias[n]
// CTA 128x128, BK=32 bf16, 3-stage cp.async pipeline, 8 warps (2m x 4n),
// warp tile 64x32, mma.sync m16n8k16 (hi*hi + hi*lo + lo*hi).
// Smem tiles: [128 rows][32 cols] bf16, row stride 40 bf16 (80B) -> ldmatrix
// conflict-free (20*r mod 32 distinct).
// ---------------------------------------------------------------------------
static constexpr int RS = 40;                       // smem row stride (bf16)
static constexpr int TILE_B = 128 * RS * 2;         // 10240 bytes per tile
static constexpr int OFF_AHI = 0;
static constexpr int OFF_ALO = TILE_B;
static constexpr int OFF_BHI = 2 * TILE_B;
static constexpr int OFF_BLO = 3 * TILE_B;
static constexpr int STAGE_B = 4 * TILE_B;          // 40960
static constexpr int NSTAGE = 3;
static constexpr int SMEM_GEMM = NSTAGE * STAGE_B;  // 122880

template<bool TRANS_OUT>
__global__ __launch_bounds__(256, 1) void gemm_hmma3_kernel(
    const __nv_bfloat16* __restrict__ Ahi_, const __nv_bfloat16* __restrict__ Alo_,
    const __nv_bfloat16* __restrict__ Bhi_, const __nv_bfloat16* __restrict__ Blo_,
    const float* __restrict__ bias, float* __restrict__ Y)
{
    extern __shared__ char smem[];
    const uint32_t sb = smem_u32(smem);
    const int tid = threadIdx.x;
    const int wid = tid >> 5, lane = tid & 31;
    const int warp_m = wid >> 2;       // 0..1 (64 rows each)
    const int warp_n = wid & 3;        // 0..3 (32 cols each)

    const int m0 = blockIdx.y * 128;
    const int n0 = blockIdx.x * 128;

    // ---- loader mapping: 256 threads x 2 rows x 4 chunks per tile ----
    // chunk c covers bf16 cols 8c..8c+7 (16B); rows r = tid/4*? :
    // per tile: 128 rows * 4 chunks = 512 chunks; thread does 2 (rows tid/4? )
    const int lrow0 = tid >> 2;            // 0..63
    const int lchunk = tid & 3;            // 0..3
    // thread handles rows lrow0 and lrow0+64 for each of 4 tiles

    const __nv_bfloat16* gA[2] = {Ahi_, Alo_};
    const __nv_bfloat16* gB[2] = {Bhi_, Blo_};

    auto issue_stage = [&](int kt, int stg) {
        const uint32_t s0 = sb + stg * STAGE_B;
        const int k0 = kt * 32;
        #pragma unroll
        for (int v = 0; v < 2; v++) {
            #pragma unroll
            for (int rr = 0; rr < 2; rr++) {
                const int r = lrow0 + rr * 64;
                // A tile
                cp_async16(s0 + (v ? OFF_ALO : OFF_AHI) + r * (RS * 2) + lchunk * 16,
                           gA[v] + (size_t)(m0 + r) * 1024 + k0 + lchunk * 8);
                // B tile
                cp_async16(s0 + (v ? OFF_BLO : OFF_BHI) + r * (RS * 2) + lchunk * 16,
                           gB[v] + (size_t)(n0 + r) * 1024 + k0 + lchunk * 8);
            }
        }
        cp_commit();
    };

    float acc[4][4][4];
    #pragma unroll
    for (int mi = 0; mi < 4; mi++)
        #pragma unroll
        for (int ni = 0; ni < 4; ni++)
            #pragma unroll
            for (int e = 0; e < 4; e++) acc[mi][ni][e] = 0.f;

    // prologue: stages 0,1
    issue_stage(0, 0);
    issue_stage(1, 1);

    // per-lane ldmatrix address components
    const int la = lane & 15;                    // A: row within 16
    const int lahalf = (lane >> 4) * 16;         // A: 0 or 16 bytes
    const int lb = ((lane & 15) & 7);            // B: row within 8
    const int lbhalf = (((lane & 15) >> 3)) * 16;

    for (int kt = 0; kt < 32; kt++) {
        cp_wait<1>();
        __syncthreads();

        if (kt + 2 < 32) issue_stage(kt + 2, (kt + 2) % NSTAGE);
        else cp_commit();   // empty group keeps wait<1> semantics aligned

        const uint32_t s0 = sb + (kt % NSTAGE) * STAGE_B;
        #pragma unroll
        for (int kk = 0; kk < 2; kk++) {
            uint32_t ah[4][4], al[4][4], bh[4][2], bl[4][2];
            #pragma unroll
            for (int mi = 0; mi < 4; mi++) {
                const uint32_t rowoff =
                    (uint32_t)(warp_m * 64 + mi * 16 + la) * (RS * 2) + lahalf + kk * 32;
                ldsm_x4(ah[mi], s0 + OFF_AHI + rowoff);
                ldsm_x4(al[mi], s0 + OFF_ALO + rowoff);
            }
            #pragma unroll
            for (int ni = 0; ni < 4; ni++) {
                const uint32_t rowoff =
                    (uint32_t)(warp_n * 32 + ni * 8 + lb) * (RS * 2) + lbhalf + kk * 32;
                ldsm_x2(bh[ni], s0 + OFF_BHI + rowoff);
                ldsm_x2(bl[ni], s0 + OFF_BLO + rowoff);
            }
            #pragma unroll
            for (int mi = 0; mi < 4; mi++)
                #pragma unroll
                for (int ni = 0; ni < 4; ni++) {
                    mma_bf16(acc[mi][ni], ah[mi], bh[ni]);
                    mma_bf16(acc[mi][ni], ah[mi], bl[ni]);
                    mma_bf16(acc[mi][ni], al[mi], bh[ni]);
                }
        }
    }

    // ---- epilogue ----
    const int lr = lane >> 2;
    const int lc = (lane & 3) * 2;
    #pragma unroll
    for (int mi = 0; mi < 4; mi++) {
        #pragma unroll
        for (int ni = 0; ni < 4; ni++) {
            const int n = n0 + warp_n * 32 + ni * 8 + lc;
            const float bx = __ldg(bias + n);
            const float by = __ldg(bias + n + 1);
            const int r0 = m0 + warp_m * 64 + mi * 16 + lr;
            const int r1 = r0 + 8;
            float2 v0 = make_float2(acc[mi][ni][0] + bx, acc[mi][ni][1] + by);
            float2 v1 = make_float2(acc[mi][ni][2] + bx, acc[mi][ni][3] + by);
            if (TRANS_OUT) {
                const int h_ = n >> 6, dk = n & 63;
                *(float2*)(Y + (((size_t)((r0 >> 10) * H_ + h_)) * S_ + (r0 & 1023)) * DK_ + dk) = v0;
                *(float2*)(Y + (((size_t)((r1 >> 10) * H_ + h_)) * S_ + (r1 & 1023)) * DK_ + dk) = v1;
            } else {
                *(float2*)(Y + (size_t)r0 * D_ + n) = v0;
                *(float2*)(Y + (size_t)r1 * D_ + n) = v1;
            }
        }
    }
}

// ---------------------------------------------------------------------------
// Flash attention (fp32) — unchanged.
// ---------------------------------------------------------------------------
#define PAD 68

__global__ __launch_bounds__(256) void flash_attn_kernel(
    const float* __restrict__ Qg_, const float* __restrict__ Kg_,
    const float* __restrict__ Vg_, const int* __restrict__ mask,
    float* __restrict__ Out)
{
    extern __shared__ float sm[];
    float* Qs = sm;
    float* Ks = sm + 64 * PAD;
    float* Vs = sm + 2 * 64 * PAD;
    float* Ps = sm + 3 * 64 * PAD;

    const int bh = blockIdx.y;
    const int b = bh >> 4;
    const int h = bh & 15;
    const int q0 = blockIdx.x * 64;
    const int tid = threadIdx.x;
    const int tx = tid & 15;
    const int ty = tid >> 4;

    const float* Qg = Qg_ + (size_t)bh * S_ * DK_;
    const float* Kg = Kg_ + (size_t)bh * S_ * DK_;
    const float* Vg = Vg_ + (size_t)bh * S_ * DK_;
    const int* Mg = mask + (size_t)b * S_ * S_;

    #pragma unroll
    for (int rep = 0; rep < 4; rep++) {
        const int idx = rep * 256 + tid;
        const int row = idx >> 4;
        const int col = (idx & 15) << 2;
        float4 qv = *(const float4*)(Qg + (size_t)(q0 + row) * DK_ + col);
        Qs[(col + 0) * PAD + row] = qv.x;
        Qs[(col + 1) * PAD + row] = qv.y;
        Qs[(col + 2) * PAD + row] = qv.z;
        Qs[(col + 3) * PAD + row] = qv.w;
    }

    float O[4][4];
    float mrow[4], lrow[4];
    #pragma unroll
    for (int i = 0; i < 4; i++) {
        mrow[i] = -1e30f;
        lrow[i] = 0.f;
        #pragma unroll
        for (int d = 0; d < 4; d++) O[i][d] = 0.f;
    }

    for (int k0 = 0; k0 < S_; k0 += 64) {
        __syncthreads();
        #pragma unroll
        for (int rep = 0; rep < 4; rep++) {
            const int idx = rep * 256 + tid;
            const int row = idx >> 4;
            const int col = (idx & 15) << 2;
            float4 kv = *(const float4*)(Kg + (size_t)(k0 + row) * DK_ + col);
            Ks[(col + 0) * PAD + row] = kv.x;
            Ks[(col + 1) * PAD + row] = kv.y;
            Ks[(col + 2) * PAD + row] = kv.z;
            Ks[(col + 3) * PAD + row] = kv.w;
            float4 vv = *(const float4*)(Vg + (size_t)(k0 + row) * DK_ + col);
            *(float4*)&Vs[row * PAD + col] = vv;
        }
        __syncthreads();

        float s[4][4];
        #pragma unroll
        for (int i = 0; i < 4; i++)
            #pragma unroll
            for (int j = 0; j < 4; j++) s[i][j] = 0.f;

        #pragma unroll 16
        for (int d = 0; d < 64; d++) {
            float4 qv = *(const float4*)&Qs[d * PAD + ty * 4];
            float4 kv = *(const float4*)&Ks[d * PAD + tx * 4];
            const float qa[4] = {qv.x, qv.y, qv.z, qv.w};
            const float ka[4] = {kv.x, kv.y, kv.z, kv.w};
            #pragma unroll
            for (int i = 0; i < 4; i++)
                #pragma unroll
                for (int j = 0; j < 4; j++)
                    s[i][j] += qa[i] * ka[j];
        }

        #pragma unroll
        for (int i = 0; i < 4; i++) {
            const int4 mv = *(const int4*)(Mg + (size_t)(q0 + ty * 4 + i) * S_ + k0 + tx * 4);
            s[i][0] = mv.x ? s[i][0] * 0.125f : -1e30f;
            s[i][1] = mv.y ? s[i][1] * 0.125f : -1e30f;
            s[i][2] = mv.z ? s[i][2] * 0.125f : -1e30f;
            s[i][3] = mv.w ? s[i][3] * 0.125f : -1e30f;
        }

        #pragma unroll
        for (int i = 0; i < 4; i++) {
            float rm = fmaxf(fmaxf(s[i][0], s[i][1]), fmaxf(s[i][2], s[i][3]));
            #pragma unroll
            for (int off = 1; off < 16; off <<= 1)
                rm = fmaxf(rm, __shfl_xor_sync(0xffffffffu, rm, off));
            const float mnew = fmaxf(mrow[i], rm);
            const float corr = __expf(mrow[i] - mnew);
            mrow[i] = mnew;
            float rs = 0.f;
            #pragma unroll
            for (int j = 0; j < 4; j++) {
                const float p = __expf(s[i][j] - mnew);
                s[i][j] = p;
                rs += p;
            }
            #pragma unroll
            for (int off = 1; off < 16; off <<= 1)
                rs += __shfl_xor_sync(0xffffffffu, rs, off);
            lrow[i] = lrow[i] * corr + rs;
            #pragma unroll
            for (int d = 0; d < 4; d++) O[i][d] *= corr;
            *(float4*)&Ps[(ty * 4 + i) * PAD + tx * 4] =
                make_float4(s[i][0], s[i][1], s[i][2], s[i][3]);
        }
        __syncthreads();

        #pragma unroll 8
        for (int kk = 0; kk < 64; kk++) {
            float4 vv = *(const float4*)&Vs[kk * PAD + tx * 4];
            const float va[4] = {vv.x, vv.y, vv.z, vv.w};
            #pragma unroll
            for (int i = 0; i < 4; i++) {
                const float p = Ps[(ty * 4 + i) * PAD + kk];
                #pragma unroll
                for (int d = 0; d < 4; d++)
                    O[i][d] += p * va[d];
            }
        }
    }

    #pragma unroll
    for (int i = 0; i < 4; i++) {
        const float inv = 1.f / lrow[i];
        float4 o4 = make_float4(O[i][0] * inv, O[i][1] * inv,
                                O[i][2] * inv, O[i][3] * inv);
        *(float4*)(Out + ((size_t)(b * S_ + q0 + ty * 4 + i)) * D_ + h * 64 + tx * 4) = o4;
    }
}

// ---------------------------------------------------------------------------
extern "C" void kernel_launch(void* const* d_in, const int* in_sizes, int n_in,
                              void* d_out, int out_size) {
    const float* query = (const float*)d_in[0];
    const float* key   = (const float*)d_in[1];
    const float* value = (const float*)d_in[2];
    const int*   mask  = (const int*)d_in[3];
    const float* wq = (const float*)d_in[4];
    const float* bq = (const float*)d_in[5];
    const float* wk = (const float*)d_in[6];
    const float* bk = (const float*)d_in[7];
    const float* wv = (const float*)d_in[8];
    const float* bv = (const float*)d_in[9];
    const float* wo = (const float*)d_in[10];
    const float* bo = (const float*)d_in[11];
    float* out = (float*)d_out;

    float *q_p, *k_p, *v_p, *ctx_p;
    __nv_bfloat16 *ahi_p, *alo_p, *bhi_p, *blo_p;
    cudaGetSymbolAddress((void**)&q_p, g_q);
    cudaGetSymbolAddress((void**)&k_p, g_k);
    cudaGetSymbolAddress((void**)&v_p, g_v);
    cudaGetSymbolAddress((void**)&ctx_p, g_ctx);
    cudaGetSymbolAddress((void**)&ahi_p, g_ahi);
    cudaGetSymbolAddress((void**)&alo_p, g_alo);
    cudaGetSymbolAddress((void**)&bhi_p, g_bhi);
    cudaGetSymbolAddress((void**)&blo_p, g_blo);

    cudaFuncSetAttribute(gemm_hmma3_kernel<true>,
                         cudaFuncAttributeMaxDynamicSharedMemorySize, SMEM_GEMM);
    cudaFuncSetAttribute(gemm_hmma3_kernel<false>,
                         cudaFuncAttributeMaxDynamicSharedMemorySize, SMEM_GEMM);

    const dim3 gemmGrid(D_ / 128, (B_ * S_) / 128);  // (8, 64)
    const int convA = (8192 * 1024 / 8) / 256;       // 4096
    const int convW = (1024 * 1024 / 8) / 256;       // 512

    // Q projection
    conv_split_kernel<<<convA, 256>>>(query, ahi_p, alo_p);
    conv_split_kernel<<<convW, 256>>>(wq, bhi_p, blo_p);
    gemm_hmma3_kernel<true><<<gemmGrid, 256, SMEM_GEMM>>>(ahi_p, alo_p, bhi_p, blo_p, bq, q_p);
    // K projection
    conv_split_kernel<<<convA, 256>>>(key, ahi_p, alo_p);
    conv_split_kernel<<<convW, 256>>>(wk, bhi_p, blo_p);
    gemm_hmma3_kernel<true><<<gemmGrid, 256, SMEM_GEMM>>>(ahi_p, alo_p, bhi_p, blo_p, bk, k_p);
    // V projection
    conv_split_kernel<<<convA, 256>>>(value, ahi_p, alo_p);
    conv_split_kernel<<<convW, 256>>>(wv, bhi_p, blo_p);
    gemm_hmma3_kernel<true><<<gemmGrid, 256, SMEM_GEMM>>>(ahi_p, alo_p, bhi_p, blo_p, bv, v_p);

    // Attention
    const int smemBytes = 4 * 64 * PAD * (int)sizeof(float);  // 69632
    cudaFuncSetAttribute(flash_attn_kernel,
                         cudaFuncAttributeMaxDynamicSharedMemorySize, smemBytes);
    flash_attn_kernel<<<dim3(S_ / 64, B_ * H_), 256, smemBytes>>>(
        q_p, k_p, v_p, mask, ctx_p);

    // Output projection
    conv_split_kernel<<<convA, 256>>>(ctx_p, ahi_p, alo_p);
    conv_split_kernel<<<convW, 256>>>(wo, bhi_p, blo_p);
    gemm_hmma3_kernel<false><<<gemmGrid, 256, SMEM_GEMM>>>(ahi_p, alo_p, bhi_p, blo_p, bo, out);
}